// round 9
// baseline (speedup 1.0000x reference)
#include <cuda_runtime.h>
#include <math.h>

// Live dataflow of the reference:
//   gu_i    = 0.2 * x0_i * gu0_i                 (fixed, D=100)
//   term3_t = dot(gu, noise[t]) * sqrt(dt_t)     (40 independent dots)
//   u_{t+1} = u_t - f(u_t)*dt_t + term3_t        (serial scalar chain)
// Output: u_40 (1 float). W1..b3 (the per-step MLPs) never reach the output.
//
// R7 probe (3rd submit; broker timeouts, never run): 320 threads
// (10 warps x 4 steps) — interpolating the block-size scan
// (1024: 5.86us, 640: 5.06us, 128: 5.47us). All loads issued before any
// arithmetic; stage-outer interleaved reductions; sqrt(dt) precomputed in
// the init phase, applied off the dependent path.

#define D 100
#define NSTEPS 40
#define NF4 25          // float4s per row (100 floats)
#define SPW 4           // steps per warp

__device__ __forceinline__ float dot4(float4 a, float4 b) {
    return fmaf(a.x, b.x, fmaf(a.y, b.y, fmaf(a.z, b.z, a.w * b.w)));
}

__global__ void __launch_bounds__(320, 1)
net2_kernel(const float* __restrict__ x0,
            const float* __restrict__ tlist,
            const float* __restrict__ noise,   // (NSTEPS, D), rows 400B, 16B aligned
            const float* __restrict__ u0,
            const float* __restrict__ gu0,     // (D, 1)
            float* __restrict__ out) {
    __shared__ float s_term3[NSTEPS];  // raw dot(gu, noise[t])
    __shared__ float s_dt[NSTEPS];
    __shared__ float s_sq[NSTEPS];     // sqrt(dt)
    __shared__ float s_Al[NSTEPS];     // 1 + (0.02/3 + 0.02)*dt
    __shared__ float s_Ah[NSTEPS];     // 1 + (0.002/3 + 0.02)*dt

    const int tid   = threadIdx.x;
    const int lane  = tid & 31;
    const int warp  = tid >> 5;        // 0..9
    const int tbase = warp * SPW;

    const float4* x0f = (const float4*)x0;
    const float4* guf = (const float4*)gu0;
    const float4* nzf = (const float4*)noise;

    // ── Issue ALL global loads first (single latency exposure) ───────────
    float4 n[SPW];
    float4 xv = make_float4(0.f, 0.f, 0.f, 0.f);
    float4 gv = xv;
    if (lane < NF4) {
        #pragma unroll
        for (int j = 0; j < SPW; ++j)
            n[j] = nzf[(tbase + j) * NF4 + lane];
        xv = x0f[lane];
        gv = guf[lane];
    } else {
        #pragma unroll
        for (int j = 0; j < SPW; ++j)
            n[j] = make_float4(0.f, 0.f, 0.f, 0.f);
    }

    // Init-phase precompute, overlapped with the load latency above.
    if (tid < NSTEPS) {
        float dt = tlist[tid];
        s_dt[tid] = dt;
        s_sq[tid] = sqrtf(dt);
        s_Al[tid] = fmaf(0.026666667f, dt, 1.0f);
        s_Ah[tid] = fmaf(0.020666667f, dt, 1.0f);
    }

    const float4 g4 = make_float4(0.2f * xv.x * gv.x, 0.2f * xv.y * gv.y,
                                  0.2f * xv.z * gv.z, 0.2f * xv.w * gv.w);

    // ── 4 dots + stage-outer interleaved shuffle reductions ──────────────
    float acc[SPW];
    #pragma unroll
    for (int j = 0; j < SPW; ++j)
        acc[j] = dot4(g4, n[j]);

    #pragma unroll
    for (int off = 16; off > 0; off >>= 1) {
        #pragma unroll
        for (int j = 0; j < SPW; ++j)
            acc[j] += __shfl_xor_sync(0xffffffffu, acc[j], off);
    }

    if (lane == 0) {
        #pragma unroll
        for (int j = 0; j < SPW; ++j)
            s_term3[tbase + j] = acc[j];
    }

    __syncthreads();

    // ── Serial branchless chain (thread 0) ───────────────────────────────
    if (tid == 0) {
        float u = u0[0];
        #pragma unroll
        for (int t = 0; t < NSTEPS; ++t) {
            const float T  = s_term3[t] * s_sq[t];   // off the dependent path
            const float dt = s_dt[t];
            // low (u < 50):   u' = u*(1 + 0.0266667*dt) + T
            const float ul = fmaf(u, s_Al[t], T);
            // high (u >= 70): u' = u*(1 + 0.0206667*dt) + T
            const float uh = fmaf(u, s_Ah[t], T);
            // mid: f(u) = u*(37.037037*(u-50) - 0.0866667)  ((u-50) exact near 50)
            const float um50 = u - 50.0f;
            const float p  = fmaf(37.037037f, um50, -0.086666667f);
            const float g  = u * p;
            const float s  = u + T;
            const float um = fmaf(-dt, g, s);
            u = (u < 50.0f) ? ul : ((u >= 70.0f) ? uh : um);
        }
        out[0] = u;
    }
}

extern "C" void kernel_launch(void* const* d_in, const int* in_sizes, int n_in,
                              void* d_out, int out_size) {
    // metadata order: x0, tlist, noise, u0, gu0, W1, b1, W2, b2, W3, b3
    const float* x0    = (const float*)d_in[0];
    const float* tlist = (const float*)d_in[1];
    const float* noise = (const float*)d_in[2];
    const float* u0    = (const float*)d_in[3];
    const float* gu0   = (const float*)d_in[4];
    float* out = (float*)d_out;
    net2_kernel<<<1, 320>>>(x0, tlist, noise, u0, gu0, out);
}

// round 10
// speedup vs baseline: 1.0854x; 1.0854x over previous
#include <cuda_runtime.h>
#include <math.h>

// Live dataflow of the reference:
//   gu_i    = 0.2 * x0_i * gu0_i                 (fixed, D=100)
//   term3_t = dot(gu, noise[t]) * sqrt(dt_t)     (40 independent dots)
//   u_{t+1} = u_t - f(u_t)*dt_t + term3_t        (serial scalar chain)
// Output: u_40 (1 float). W1..b3 (the per-step MLPs) never reach the output.
//
// R10 = exact revert to the best measured config (R4):
// 640 threads (20 warps x 2 steps), float4 loads (25 LDG.128 per step),
// all loads in flight before any reduction, branchless folded recurrence.
// Block-size scan (same body): 1024->5.86us, 640->5.06us, 320->5.86us,
// 128->5.47us — differences within run-to-run noise; 640 is best observed.

#define D 100
#define NSTEPS 40
#define NF4 25          // float4s per row (100 floats)

__device__ __forceinline__ float dot4(float4 a, float4 b) {
    return fmaf(a.x, b.x, fmaf(a.y, b.y, fmaf(a.z, b.z, a.w * b.w)));
}

__global__ void __launch_bounds__(640, 1)
net2_kernel(const float* __restrict__ x0,
            const float* __restrict__ tlist,
            const float* __restrict__ noise,   // (NSTEPS, D), rows 400B = 16B aligned
            const float* __restrict__ u0,
            const float* __restrict__ gu0,     // (D, 1)
            float* __restrict__ out) {
    __shared__ float s_term3[NSTEPS];
    __shared__ float s_dt[NSTEPS];
    __shared__ float s_Al[NSTEPS];   // 1 + (0.02/3 + 0.02)*dt
    __shared__ float s_Ah[NSTEPS];   // 1 + (0.002/3 + 0.02)*dt

    const int tid  = threadIdx.x;
    const int lane = tid & 31;
    const int warp = tid >> 5;       // 0..19

    if (tid < NSTEPS) {
        float dt = tlist[tid];
        s_dt[tid] = dt;
        s_Al[tid] = fmaf(0.026666667f, dt, 1.0f);
        s_Ah[tid] = fmaf(0.020666667f, dt, 1.0f);
    }

    const int t0 = warp * 2;
    const int t1 = t0 + 1;
    const float dt0 = tlist[t0];     // L1-broadcast, off critical path
    const float dt1 = tlist[t1];

    const float4* x0f  = (const float4*)x0;
    const float4* guf  = (const float4*)gu0;
    const float4* nzf  = (const float4*)noise;

    // Issue ALL loads before any arithmetic/reduction.
    float4 g4 = make_float4(0.f, 0.f, 0.f, 0.f);
    float4 n0 = make_float4(0.f, 0.f, 0.f, 0.f);
    float4 n1 = make_float4(0.f, 0.f, 0.f, 0.f);
    if (lane < NF4) {
        float4 xv = x0f[lane];
        float4 gv = guf[lane];
        n0 = nzf[t0 * NF4 + lane];
        n1 = nzf[t1 * NF4 + lane];
        g4 = make_float4(0.2f * xv.x * gv.x, 0.2f * xv.y * gv.y,
                         0.2f * xv.z * gv.z, 0.2f * xv.w * gv.w);
    }

    float acc0 = dot4(g4, n0);
    #pragma unroll
    for (int off = 16; off > 0; off >>= 1)
        acc0 += __shfl_xor_sync(0xffffffffu, acc0, off);
    if (lane == 0)
        s_term3[t0] = acc0 * sqrtf(dt0);

    float acc1 = dot4(g4, n1);
    #pragma unroll
    for (int off = 16; off > 0; off >>= 1)
        acc1 += __shfl_xor_sync(0xffffffffu, acc1, off);
    if (lane == 0)
        s_term3[t1] = acc1 * sqrtf(dt1);

    __syncthreads();

    if (tid == 0) {
        float u = u0[0];
        #pragma unroll
        for (int t = 0; t < NSTEPS; ++t) {
            const float T  = s_term3[t];
            const float dt = s_dt[t];
            // low (u < 50):   u' = u*(1 + 0.0266667*dt) + T
            const float ul = fmaf(u, s_Al[t], T);
            // high (u >= 70): u' = u*(1 + 0.0206667*dt) + T
            const float uh = fmaf(u, s_Ah[t], T);
            // mid: f(u) = u*(37.037037*(u-50) - 0.0866667)   ((u-50) exact near 50)
            const float um50 = u - 50.0f;
            const float p  = fmaf(37.037037f, um50, -0.086666667f);
            const float g  = u * p;
            const float s  = u + T;                 // off the critical path
            const float um = fmaf(-dt, g, s);
            u = (u < 50.0f) ? ul : ((u >= 70.0f) ? uh : um);
        }
        out[0] = u;
    }
}

extern "C" void kernel_launch(void* const* d_in, const int* in_sizes, int n_in,
                              void* d_out, int out_size) {
    // metadata order: x0, tlist, noise, u0, gu0, W1, b1, W2, b2, W3, b3
    const float* x0    = (const float*)d_in[0];
    const float* tlist = (const float*)d_in[1];
    const float* noise = (const float*)d_in[2];
    const float* u0    = (const float*)d_in[3];
    const float* gu0   = (const float*)d_in[4];
    float* out = (float*)d_out;
    net2_kernel<<<1, 640>>>(x0, tlist, noise, u0, gu0, out);
}